// round 16
// baseline (speedup 1.0000x reference)
#include <cuda_runtime.h>
#include <cuda_fp16.h>
#include <cstdint>

// Problem constants
#define NJ 52
#define NB 32
#define MT 128           // vertices per tile (GEMM M tile)
#define NTG 48           // n-tiles of 8 (total N = 384 permuted cols)
#define THREADS 256      // 8 warps: 4 (M) x 2 (N)
#define NCHUNK 4         // N chunks of 96 cols
#define A_LD 7           // uint4 loads per thread for one A tile (ceil(1664/256))
#define GRID_P 296       // persistent CTAs (2 per SM x 148)

// SMEM: two A buffers (fp16, SW128) + staged B fragments
#define S_A0 0
#define S_A1 (MT * 128)                     // 16384
#define S_B  (2 * MT * 128)                 // 32768
#define S_TOTAL (S_B + NTG * 4 * 32 * 8)    // 32768 + 49152 = 81920

#define SW128(b) ((b) ^ (((b) >> 3) & 0x70))

// B fragments (fp16): [ntg][kt][lane] -> uint2 {b0,b1}
// Column permutation: within 48-col group g, position p = 8t+2q+d holds
// (batch 4g+q, element e = 2t+d), e = i*4+k over rows 0..2 of the 4x4.
__device__ __align__(16) uint2 g_Bf[NTG * 4 * 32];

__device__ __forceinline__ uint32_t smem_u32(const void* p) {
    uint32_t a;
    asm("{ .reg .u64 t; cvta.to.shared.u64 t, %1; cvt.u32.u64 %0, t; }"
        : "=r"(a) : "l"(p));
    return a;
}

__device__ __forceinline__ void ldsm_x4(uint32_t* d, uint32_t addr) {
    asm volatile("ldmatrix.sync.aligned.m8n8.x4.shared.b16 {%0,%1,%2,%3}, [%4];"
                 : "=r"(d[0]), "=r"(d[1]), "=r"(d[2]), "=r"(d[3]) : "r"(addr));
}

__device__ __forceinline__ void ldsm_x2(uint32_t& d0, uint32_t& d1, uint32_t addr) {
    asm volatile("ldmatrix.sync.aligned.m8n8.x2.shared.b16 {%0,%1}, [%2];"
                 : "=r"(d0), "=r"(d1) : "r"(addr));
}

__device__ __forceinline__ void mma_f16(float* c, const uint32_t* a,
                                        uint32_t b0, uint32_t b1) {
    asm volatile(
        "mma.sync.aligned.m16n8k16.row.col.f32.f16.f16.f32 "
        "{%0,%1,%2,%3}, {%4,%5,%6,%7}, {%8,%9}, {%0,%1,%2,%3};"
        : "+f"(c[0]), "+f"(c[1]), "+f"(c[2]), "+f"(c[3])
        : "r"(a[0]), "r"(a[1]), "r"(a[2]), "r"(a[3]), "r"(b0), "r"(b1));
}

// ---------------- Prep kernel: build permuted B fragments (48 CTAs) ---------
__global__ void __launch_bounds__(THREADS)
prep_B_kernel(const float* __restrict__ M) {
    __shared__ __align__(128) char pb[8 * 128];   // 8 rows x 128B (fp16 K=64)
    const int tid = threadIdx.x;
    const int lane = tid & 31;
    const int ntg = blockIdx.x;

    if (tid < 8 * 32) {                 // one (row, col-pair) per thread
        const int nl = tid >> 5;        // local n row 0..7 = 2q+d
        const int jp = tid & 31;
        const int g = ntg / 6;
        const int t = ntg - g * 6;
        const int b = 4 * g + (nl >> 1);   // batch
        const int e = 2 * t + (nl & 1);    // element 0..11
        const int j0 = 2 * jp, j1 = 2 * jp + 1;
        float m0 = (j0 < NJ) ? M[((size_t)b * NJ + j0) * 16 + e] : 0.0f;
        float m1 = (j1 < NJ) ? M[((size_t)b * NJ + j1) * 16 + e] : 0.0f;
        __half2 hp;
        hp.x = __float2half(m0);
        hp.y = __float2half(m1);
        uint32_t off = SW128((uint32_t)(nl * 128 + jp * 4));
        *reinterpret_cast<__half2*>(pb + off) = hp;
    }
    __syncthreads();

    if (tid < 32) {
        const uint32_t sbp = smem_u32(pb);
        const int bsub = (lane >> 3) & 1;
        const int brin = lane & 7;
        #pragma unroll
        for (int kt = 0; kt < 4; kt++) {
            const uint32_t byte = (uint32_t)(brin * 128 + kt * 32 + bsub * 16);
            const uint32_t sw = SW128(byte);
            uint32_t b0, b1;
            ldsm_x2(b0, b1, sbp + sw);
            g_Bf[(ntg * 4 + kt) * 32 + lane] = make_uint2(b0, b1);
        }
    }
}

// ---- A-tile helpers --------------------------------------------------------
__device__ __forceinline__ void loadA_raw(uint4* raw, const float* __restrict__ W,
                                          int vbase, int V, int tid) {
    const uint4* wp4 = reinterpret_cast<const uint4*>(W + (size_t)vbase * NJ);
    const int lim4 = (V - vbase) * (NJ / 4);
    #pragma unroll
    for (int u = 0; u < A_LD; u++) {
        const int i = tid + u * THREADS;
        raw[u] = (i < MT * (NJ / 4) && i < lim4) ? wp4[i] : make_uint4(0, 0, 0, 0);
    }
}

__device__ __forceinline__ void storeA_conv(const uint4* raw, char* smem,
                                            uint32_t sbuf_off, int tid) {
    #pragma unroll
    for (int u = 0; u < A_LD; u++) {
        const int i = tid + u * THREADS;
        if (i < MT * (NJ / 4)) {
            const int r = i / (NJ / 4);
            const int q = i - r * (NJ / 4);
            const float* f = reinterpret_cast<const float*>(&raw[u]);
            __half2 p0, p1;
            p0.x = __float2half(f[0]); p0.y = __float2half(f[1]);
            p1.x = __float2half(f[2]); p1.y = __float2half(f[3]);
            uint2 packed;
            packed.x = *reinterpret_cast<const uint32_t*>(&p0);
            packed.y = *reinterpret_cast<const uint32_t*>(&p1);
            const uint32_t off = SW128((uint32_t)(r * 128 + q * 8));
            *reinterpret_cast<uint2*>(smem + sbuf_off + off) = packed;
        }
    }
}

// ---------------- Main kernel (persistent CTAs) -----------------------------
__global__ void __launch_bounds__(THREADS, 2)
skin_mma_kernel(const float* __restrict__ verts,   // [V,3]
                const float* __restrict__ W,       // [V,NJ]
                float* __restrict__ out,           // [NB,V,3]
                int V, int ntiles) {
    extern __shared__ char smem[];
    const uint32_t sb = smem_u32(smem);
    const int tid = threadIdx.x;
    const int lane = tid & 31;
    const int wid = tid >> 5;
    const int warp_m = wid >> 1;     // 0..3
    const int warp_n = wid & 1;      // 0..1
    const int stride = gridDim.x;

    // ---- Stage B fragments into smem once per CTA (48KB, coalesced) ----
    {
        const uint4* src = reinterpret_cast<const uint4*>(g_Bf);
        uint4* dst = reinterpret_cast<uint4*>(smem + S_B);
        #pragma unroll
        for (int i = 0; i < (NTG * 4 * 32 * 8) / 16 / THREADS; i++)
            dst[tid + i * THREADS] = src[tid + i * THREADS];
    }

    // ---- Zero K-pad bytes 104..127 of BOTH A buffers (stay zero forever) ----
    {
        const uint2 z = make_uint2(0, 0);
        for (int i = tid; i < MT * 3 * 2; i += THREADS) {
            const int buf = (i >= MT * 3);
            const int k = buf ? (i - MT * 3) : i;
            const int r = k / 3;
            const int q = k - r * 3;
            const uint32_t off = SW128((uint32_t)(r * 128 + 104 + q * 8));
            *reinterpret_cast<uint2*>(smem + (buf ? S_A1 : S_A0) + off) = z;
        }
    }

    int tile = blockIdx.x;
    if (tile >= ntiles) return;

    // ---- Prologue: fill A buffer 0 for first tile ----
    uint4 raw[A_LD];
    loadA_raw(raw, W, tile * MT, V, tid);
    storeA_conv(raw, smem, S_A0, tid);
    __syncthreads();

    // A fragment swizzled base offset (within a buffer)
    uint32_t aSw[2];
    {
        const int sub = lane >> 3;
        const int rin = lane & 7;
        #pragma unroll
        for (int mt = 0; mt < 2; mt++) {
            const int row = warp_m * 32 + mt * 16 + rin + (sub & 1) * 8;
            aSw[mt] = SW128((uint32_t)(row * 128 + (sub >> 1) * 16));
        }
    }
    const int q = lane & 3;
    const int rg = lane >> 2;

    int cur = 0;
    #pragma unroll 1
    for (; tile < ntiles; tile += stride) {
        const int vbase = tile * MT;
        const int ntile = tile + stride;
        const bool have_next = (ntile < ntiles);

        // Fire next tile's A loads early (latency hides behind mma+fold)
        if (have_next) loadA_raw(raw, W, ntile * MT, V, tid);

        // A fragments for current tile
        const uint32_t abase = sb + (cur ? S_A1 : S_A0);
        uint32_t ah[2][4][4];
        #pragma unroll
        for (int mt = 0; mt < 2; mt++)
            #pragma unroll
            for (int kt = 0; kt < 4; kt++)
                ldsm_x4(ah[mt][kt], (abase + aSw[mt]) ^ (uint32_t)(kt * 32));

        // ---- N chunks: B via LDS.64, mma, in-register fold ----
        #pragma unroll 1
        for (int c = 0; c < NCHUNK; c++) {
            const uint2* bp = reinterpret_cast<const uint2*>(smem + S_B) +
                              ((size_t)(c * 12 + warp_n * 6) * 4) * 32 + lane;
            float acc[2][6][4] = {};

            #pragma unroll
            for (int kt = 0; kt < 4; kt++) {
                #pragma unroll
                for (int nt = 0; nt < 6; nt++) {
                    const uint2 bb = bp[nt * 128 + kt * 32];
                    mma_f16(acc[0][nt], ah[0][kt], bb.x, bb.y);
                    mma_f16(acc[1][nt], ah[1][kt], bb.x, bb.y);
                }
            }

            const int b = 8 * c + 4 * warp_n + q;
            #pragma unroll
            for (int rr = 0; rr < 4; rr++) {
                const int mt = rr >> 1;
                const int hb = (rr & 1) * 2;
                const int row = warp_m * 32 + mt * 16 + (rr & 1) * 8 + rg;
                const int v = vbase + row;
                if (v < V) {
                    const float x = verts[(size_t)v * 3 + 0];
                    const float y = verts[(size_t)v * 3 + 1];
                    const float z = verts[(size_t)v * 3 + 2];
                    const float o0 = fmaf(acc[mt][0][hb], x, fmaf(acc[mt][0][hb + 1], y,
                                     fmaf(acc[mt][1][hb], z, acc[mt][1][hb + 1])));
                    const float o1 = fmaf(acc[mt][2][hb], x, fmaf(acc[mt][2][hb + 1], y,
                                     fmaf(acc[mt][3][hb], z, acc[mt][3][hb + 1])));
                    const float o2 = fmaf(acc[mt][4][hb], x, fmaf(acc[mt][4][hb + 1], y,
                                     fmaf(acc[mt][5][hb], z, acc[mt][5][hb + 1])));
                    float* op = out + ((size_t)b * V + v) * 3;
                    op[0] = o0; op[1] = o1; op[2] = o2;
                }
            }
        }

        // Convert + store next tile's A into the other buffer, then sync
        if (have_next) {
            storeA_conv(raw, smem, cur ? S_A0 : S_A1, tid);
            __syncthreads();
            cur ^= 1;
        }
    }
}

extern "C" void kernel_launch(void* const* d_in, const int* in_sizes, int n_in,
                              void* d_out, int out_size) {
    const float* verts = (const float*)d_in[0];   // [1,V,3]
    const float* W     = (const float*)d_in[1];   // [1,V,NJ]
    const float* M     = (const float*)d_in[2];   // [NB,NJ,4,4]
    float* out         = (float*)d_out;           // [NB,V,3]

    const int V = in_sizes[0] / 3;
    const int ntiles = (V + MT - 1) / MT;
    const int grid = (ntiles < GRID_P) ? ntiles : GRID_P;

    cudaFuncSetAttribute(skin_mma_kernel,
                         cudaFuncAttributeMaxDynamicSharedMemorySize, S_TOTAL);

    prep_B_kernel<<<NTG, THREADS>>>(M);
    skin_mma_kernel<<<grid, THREADS, S_TOTAL>>>(verts, W, out, V, ntiles);
}